// round 5
// baseline (speedup 1.0000x reference)
#include <cuda_runtime.h>

#define BB 256
#define LL 512
#define DD 64
#define NSPLIT 4                 // quarters per batch
#define NBLK (BB * NSPLIT)       // 1024 blocks
#define ROWS_PER_BLK (LL / NSPLIT) // 128
#define EPS_LOG 1e-7f
#define EPS_COS 1e-8f

__device__ float g_m[NBLK];
__device__ float g_pos[NBLK];
__device__ float g_neg[NBLK];
__device__ int   g_cnt = 0;

__global__ __launch_bounds__(256)
void wnl_fused(const float* __restrict__ emb,
               const float* __restrict__ probs,
               const float* __restrict__ labels,
               float* __restrict__ out)
{
    const int bid  = blockIdx.x;          // 0..1023
    const int b    = bid >> 2;            // batch 0..255
    const int qtr  = bid & 3;             // quarter 0..3
    const int tid  = threadIdx.x;         // 0..255
    const int wid  = tid >> 5;            // 0..7
    const int lane = tid & 31;
    const int g    = lane >> 2;           // 8 row-groups per warp
    const int s    = lane & 3;            // 4 lanes per row

    __shared__ float s_q[DD];
    __shared__ float s_m[8], s_pos[8], s_neg[8], s_sum[8];
    __shared__ int   s_last;

    const float* __restrict__ embB = emb    + (size_t)b * LL * DD;
    const float* __restrict__ labB = labels + (size_t)b * LL;
    const float* __restrict__ prbB = probs  + (size_t)b * LL;

    // query row q = emb[b][b][:]
    if (tid < DD) s_q[tid] = embB[b * DD + tid];
    if (tid == 0) s_last = 0;
    __syncthreads();

    // lane owns 4 interleaved float4s: q[j*16 + s*4 .. +4), j = 0..3
    const float4 q0 = *(const float4*)&s_q[ 0 + s * 4];
    const float4 q1 = *(const float4*)&s_q[16 + s * 4];
    const float4 q2 = *(const float4*)&s_q[32 + s * 4];
    const float4 q3 = *(const float4*)&s_q[48 + s * 4];

    // ||q||^2 via 4-lane butterfly
    float nq2 = q0.x*q0.x + q0.y*q0.y + q0.z*q0.z + q0.w*q0.w
              + q1.x*q1.x + q1.y*q1.y + q1.z*q1.z + q1.w*q1.w
              + q2.x*q2.x + q2.y*q2.y + q2.z*q2.z + q2.w*q2.w
              + q3.x*q3.x + q3.y*q3.y + q3.z*q3.z + q3.w*q3.w;
    nq2 += __shfl_xor_sync(0xffffffffu, nq2, 2);
    nq2 += __shfl_xor_sync(0xffffffffu, nq2, 1);
    const float nq = sqrtf(nq2);

    // ---- masked row-max of relu(cos) over this quarter's 128 rows ----
    // warp w covers 16 rows; 8 rows per iteration (one per group g), 2 iters
    float m = 0.f;
    const int rowBase = qtr * ROWS_PER_BLK + wid * 16;
    #pragma unroll
    for (int it = 0; it < 2; it++) {
        const int k = rowBase + it * 8 + g;
        const float* rp = embB + (size_t)k * DD;
        // each instruction: 8 rows x 64B contiguous -> fully coalesced
        const float4 x0 = *(const float4*)(rp +  0 + s * 4);
        const float4 x1 = *(const float4*)(rp + 16 + s * 4);
        const float4 x2 = *(const float4*)(rp + 32 + s * 4);
        const float4 x3 = *(const float4*)(rp + 48 + s * 4);
        float d = q0.x*x0.x + q0.y*x0.y + q0.z*x0.z + q0.w*x0.w
                + q1.x*x1.x + q1.y*x1.y + q1.z*x1.z + q1.w*x1.w
                + q2.x*x2.x + q2.y*x2.y + q2.z*x2.z + q2.w*x2.w
                + q3.x*x3.x + q3.y*x3.y + q3.z*x3.z + q3.w*x3.w;
        float n = x0.x*x0.x + x0.y*x0.y + x0.z*x0.z + x0.w*x0.w
                + x1.x*x1.x + x1.y*x1.y + x1.z*x1.z + x1.w*x1.w
                + x2.x*x2.x + x2.y*x2.y + x2.z*x2.z + x2.w*x2.w
                + x3.x*x3.x + x3.y*x3.y + x3.z*x3.z + x3.w*x3.w;
        d += __shfl_xor_sync(0xffffffffu, d, 2);
        n += __shfl_xor_sync(0xffffffffu, n, 2);
        d += __shfl_xor_sync(0xffffffffu, d, 1);
        n += __shfl_xor_sync(0xffffffffu, n, 1);
        const float lab  = __ldg(&labB[k]);
        const float cosv = d / fmaxf(nq * sqrtf(n), EPS_COS);
        m = fmaxf(m, fmaxf(cosv, 0.f) * lab);
    }

    // ---- this quarter's log sums (threads 0..127 own one l each) ----
    float pos = 0.f, neg = 0.f;
    if (tid < ROWS_PER_BLK) {
        const int   l  = qtr * ROWS_PER_BLK + tid;
        const float pe = prbB[l] + EPS_LOG;
        pos = labB[l] * logf(pe);
        neg = logf(1.0f - pe);
    }

    // warp combine
    #pragma unroll
    for (int o = 16; o; o >>= 1) {
        m    = fmaxf(m, __shfl_xor_sync(0xffffffffu, m, o));
        pos += __shfl_xor_sync(0xffffffffu, pos, o);
        neg += __shfl_xor_sync(0xffffffffu, neg, o);
    }
    if (lane == 0) { s_m[wid] = m; s_pos[wid] = pos; s_neg[wid] = neg; }
    __syncthreads();

    if (wid == 0) {
        float mm = (lane < 8) ? s_m[lane]   : 0.f;
        float pp = (lane < 8) ? s_pos[lane] : 0.f;
        float nn = (lane < 8) ? s_neg[lane] : 0.f;
        #pragma unroll
        for (int o = 4; o; o >>= 1) {
            mm = fmaxf(mm, __shfl_xor_sync(0xffffffffu, mm, o));
            pp += __shfl_xor_sync(0xffffffffu, pp, o);
            nn += __shfl_xor_sync(0xffffffffu, nn, o);
        }
        if (lane == 0) {
            g_m[bid] = mm; g_pos[bid] = pp; g_neg[bid] = nn;
            __threadfence();
            const int old = atomicAdd(&g_cnt, 1);
            if (old == NBLK - 1) s_last = 1;   // this block finishes the job
        }
    }
    __syncthreads();

    // ---- last-block final combine (deterministic fixed-order sum) ----
    if (s_last) {
        __threadfence();
        const int b2 = tid;                   // one batch per thread
        float mm = __ldcg(&g_m[4*b2]);
        float pp = __ldcg(&g_pos[4*b2]);
        float nn = __ldcg(&g_neg[4*b2]);
        #pragma unroll
        for (int j = 1; j < NSPLIT; j++) {
            mm = fmaxf(mm, __ldcg(&g_m[4*b2 + j]));
            pp += __ldcg(&g_pos[4*b2 + j]);
            nn += __ldcg(&g_neg[4*b2 + j]);
        }
        const float labdiag = __ldg(&labels[(size_t)b2 * LL + b2]);
        const float wnl = (labdiag == 0.f) ? mm : 0.f;
        float contrib = -pp - wnl * nn;

        #pragma unroll
        for (int o = 16; o; o >>= 1)
            contrib += __shfl_xor_sync(0xffffffffu, contrib, o);
        if (lane == 0) s_sum[wid] = contrib;
        __syncthreads();
        if (wid == 0) {
            float t = (lane < 8) ? s_sum[lane] : 0.f;
            #pragma unroll
            for (int o = 4; o; o >>= 1) t += __shfl_xor_sync(0xffffffffu, t, o);
            if (lane == 0) {
                out[0] = t / (float)BB;
                g_cnt = 0;                    // reset for next graph replay
            }
        }
    }
}

extern "C" void kernel_launch(void* const* d_in, const int* in_sizes, int n_in,
                              void* d_out, int out_size)
{
    const float* emb    = (const float*)d_in[0]; // (256, 512, 64) f32
    const float* probs  = (const float*)d_in[1]; // (256, 512) f32
    const float* labels = (const float*)d_in[2]; // (256, 512) f32
    float* out = (float*)d_out;                  // scalar f32

    wnl_fused<<<NBLK, 256>>>(emb, probs, labels, out);
}